// round 4
// baseline (speedup 1.0000x reference)
#include <cuda_runtime.h>
#include <math.h>

#define NPIX 16384        // 128*128
#define NCH 512
#define NCLASS 5
#define IGNORE_LBL 5
#define MV_BG 4096
#define MV 2048
#define MTOT 12288        // 4096 + 4*2048
#define ANCH_DIM 256

// -------- scratch (device globals; no allocation allowed) --------
__device__ int   g_yhat [NPIX];
__device__ int   g_order[MTOT];
__device__ int   g_ycls [MTOT];
__device__ float g_X [MTOT * 512];
__device__ float g_H1[MTOT * 512];
__device__ float g_H2[MTOT * 256];
__device__ float g_H3[MTOT * 256];

// -------- stage 1: strided argmax over labels[0, ::8, ::8, :] --------
__global__ void argmax_kernel(const float* __restrict__ labels) {
    int p = blockIdx.x * blockDim.x + threadIdx.x;   // 0..16383
    if (p >= NPIX) return;
    int i = p >> 7, j = p & 127;
    // labels index (batch 0): (i*8)*1024*5 + (j*8)*5 + c
    const float* L = labels + (size_t)i * 40960 + (size_t)j * 40;
    float best = L[0];
    int bi = 0;
#pragma unroll
    for (int c = 1; c < NCLASS; c++) {
        float v = L[c];
        if (v > best) { best = v; bi = c; }
    }
    g_yhat[p] = bi;
}

// -------- stage 2: stratified selection per class (one block per class) ----
__global__ void select_kernel(const int* __restrict__ pred) {
    const int c    = blockIdx.x;
    const int mv   = (c == 0) ? MV_BG : MV;
    const int base = (c == 0) ? 0 : MV_BG + (c - 1) * MV;
    const int t = threadIdx.x;            // 512 threads
    const int PPT = NPIX / 512;           // 32 pixels per thread

    __shared__ int sh[512], se[512];
    __shared__ int s_hk, s_ek, s_nsel;

    const int p0 = t * PPT;
    int lh = 0, le = 0;
    for (int i = 0; i < PPT; i++) {
        int p = p0 + i;
        int m = (g_yhat[p] == c);
        int e = m && (pred[p] == c);
        int h = m && !e;
        lh += h; le += e;
    }
    sh[t] = lh; se[t] = le;
    __syncthreads();
    // inclusive block scan (Hillis-Steele)
    for (int off = 1; off < 512; off <<= 1) {
        int vh = (t >= off) ? sh[t - off] : 0;
        int ve = (t >= off) ? se[t - off] : 0;
        __syncthreads();
        sh[t] += vh; se[t] += ve;
        __syncthreads();
    }
    const int hoff = sh[t] - lh;
    const int eoff = se[t] - le;
    const int nh = sh[511], ne = se[511];
    if (t == 0) {
        int cnt = nh + ne;
        int n_sel = (cnt > 1) ? min(cnt, mv) : 0;
        int hk;
        if (2 * nh >= n_sel && 2 * ne >= n_sel) hk = n_sel >> 1;
        else if (2 * nh >= n_sel)               hk = n_sel - ne;
        else                                     hk = nh;
        s_hk = hk; s_ek = n_sel - hk; s_nsel = n_sel;
    }
    __syncthreads();
    const int hk = s_hk, ek = s_ek, nsel = s_nsel;

    // defaults for pad rows + class labels for all rows
    for (int r = t; r < mv; r += 512) {
        g_ycls[base + r] = (r < nsel) ? c : IGNORE_LBL;
        if (r >= nsel) g_order[base + r] = -1;
    }

    // pass 2: write selected pixel indices in index order
    int hr = hoff, er = eoff;
    for (int i = 0; i < PPT; i++) {
        int p = p0 + i;
        if (g_yhat[p] == c) {
            if (pred[p] == c) { if (er < ek) g_order[base + hk + er] = p; er++; }
            else              { if (hr < hk) g_order[base + hr]     = p; hr++; }
        }
    }
}

// -------- stage 3: gather X[r, c] = feats[0, c, p_r] (CHW -> row-major) ----
__global__ void gather_kernel(const float* __restrict__ feats) {
    const int rb = blockIdx.x * 8;          // 8 rows per block
    const int c  = threadIdx.x;             // 256 threads, 2 channels each
#pragma unroll
    for (int rr = 0; rr < 8; rr++) {
        const int r = rb + rr;
        const int p = g_order[r];
        float v0 = 0.f, v1 = 0.f;
        if (p >= 0) {
            v0 = __ldg(feats + (size_t)c * NPIX + p);
            v1 = __ldg(feats + (size_t)(c + 256) * NPIX + p);
        }
        g_X[(size_t)r * 512 + c]       = v0;
        g_X[(size_t)r * 512 + c + 256] = v1;
    }
}

// -------- stage 4: SGEMM  C[m,n] = act( sum_k A[m,k] * W[n,k] + bias[n] ) ---
// BM=BN=64, BK=16, 256 threads, 4x4 per thread.
template <int ACT>
__global__ __launch_bounds__(256) void gemm_kernel(
    const float* __restrict__ A, const float* __restrict__ W,
    const float* __restrict__ bias, float* __restrict__ C,
    int M, int N, int K)
{
    const int BK = 16;
    __shared__ float As[16][68];
    __shared__ float Bs[16][68];

    const int tid = threadIdx.x;
    const int tx = tid & 15, ty = tid >> 4;
    const int m0 = blockIdx.y * 64, n0 = blockIdx.x * 64;

    const int lRow = tid >> 2;           // 0..63
    const int lK   = (tid & 3) * 4;      // 0,4,8,12

    const float* Ag = A + (size_t)(m0 + lRow) * K + lK;
    const float* Wg = W + (size_t)(n0 + lRow) * K + lK;

    float acc[4][4];
#pragma unroll
    for (int i = 0; i < 4; i++)
#pragma unroll
        for (int j = 0; j < 4; j++) acc[i][j] = 0.f;

    for (int k0 = 0; k0 < K; k0 += BK) {
        float4 av = *(const float4*)(Ag + k0);
        float4 wv = *(const float4*)(Wg + k0);
        As[lK + 0][lRow] = av.x; As[lK + 1][lRow] = av.y;
        As[lK + 2][lRow] = av.z; As[lK + 3][lRow] = av.w;
        Bs[lK + 0][lRow] = wv.x; Bs[lK + 1][lRow] = wv.y;
        Bs[lK + 2][lRow] = wv.z; Bs[lK + 3][lRow] = wv.w;
        __syncthreads();
#pragma unroll
        for (int k = 0; k < BK; k++) {
            float4 a4 = *(const float4*)&As[k][ty * 4];
            float4 b4 = *(const float4*)&Bs[k][tx * 4];
            float a[4] = {a4.x, a4.y, a4.z, a4.w};
            float b[4] = {b4.x, b4.y, b4.z, b4.w};
#pragma unroll
            for (int i = 0; i < 4; i++)
#pragma unroll
                for (int j = 0; j < 4; j++) acc[i][j] += a[i] * b[j];
        }
        __syncthreads();
    }

#pragma unroll
    for (int i = 0; i < 4; i++) {
        const int m = m0 + ty * 4 + i;
#pragma unroll
        for (int j = 0; j < 4; j++) {
            const int n = n0 + tx * 4 + j;
            float v = acc[i][j] + bias[n];
            if (ACT == 1) v = (v >= 0.f) ? v : 0.2f * v;
            C[(size_t)m * N + n] = v;
        }
    }
}

// -------- stage 5: row L2-normalize + emit y_ as float --------------------
__global__ void norm_kernel(float* __restrict__ out, int out_size) {
    const int warp = threadIdx.x >> 5, lane = threadIdx.x & 31;
    const int r = blockIdx.x * 8 + warp;
    if (r >= MTOT) return;
    const float4* row = (const float4*)(g_H3 + (size_t)r * 256);
    float4 v0 = row[lane * 2], v1 = row[lane * 2 + 1];
    float ss = v0.x * v0.x + v0.y * v0.y + v0.z * v0.z + v0.w * v0.w
             + v1.x * v1.x + v1.y * v1.y + v1.z * v1.z + v1.w * v1.w;
#pragma unroll
    for (int o = 16; o; o >>= 1) ss += __shfl_xor_sync(0xffffffffu, ss, o);
    float nrm = fmaxf(sqrtf(ss), 1e-12f);
    float inv = 1.0f / nrm;
    v0.x *= inv; v0.y *= inv; v0.z *= inv; v0.w *= inv;
    v1.x *= inv; v1.y *= inv; v1.z *= inv; v1.w *= inv;
    float4* orow = (float4*)(out + (size_t)r * 256);
    orow[lane * 2]     = v0;
    orow[lane * 2 + 1] = v1;
    if (lane == 0 && out_size >= MTOT * ANCH_DIM + MTOT)
        out[MTOT * ANCH_DIM + r] = (float)g_ycls[r];
}

// ---------------------------------------------------------------------------
extern "C" void kernel_launch(void* const* d_in, const int* in_sizes, int n_in,
                              void* d_out, int out_size)
{
    const float* feats   = (const float*)d_in[0];
    const float* labels  = (const float*)d_in[1];
    const int*   predicts= (const int*)  d_in[2];
    const float* w1 = (const float*)d_in[3];
    const float* b1 = (const float*)d_in[4];
    const float* w2 = (const float*)d_in[5];
    const float* b2 = (const float*)d_in[6];
    const float* w3 = (const float*)d_in[7];
    const float* b3 = (const float*)d_in[8];
    float* out = (float*)d_out;

    float *X, *H1, *H2, *H3;
    cudaGetSymbolAddress((void**)&X,  g_X);
    cudaGetSymbolAddress((void**)&H1, g_H1);
    cudaGetSymbolAddress((void**)&H2, g_H2);
    cudaGetSymbolAddress((void**)&H3, g_H3);

    argmax_kernel<<<NPIX / 256, 256>>>(labels);
    select_kernel<<<NCLASS, 512>>>(predicts);
    gather_kernel<<<MTOT / 8, 256>>>(feats);

    // layer 1: [12288,512] x [512,512]^T -> [12288,512], leaky
    gemm_kernel<1><<<dim3(512 / 64, MTOT / 64), 256>>>(X,  w1, b1, H1, MTOT, 512, 512);
    // layer 2: [12288,512] x [256,512]^T -> [12288,256], leaky
    gemm_kernel<1><<<dim3(256 / 64, MTOT / 64), 256>>>(H1, w2, b2, H2, MTOT, 256, 512);
    // layer 3: [12288,256] x [256,256]^T -> [12288,256], linear
    gemm_kernel<0><<<dim3(256 / 64, MTOT / 64), 256>>>(H2, w3, b3, H3, MTOT, 256, 256);

    norm_kernel<<<MTOT / 8, 256>>>(out, out_size);
}

// round 8
// speedup vs baseline: 1.7741x; 1.7741x over previous
#include <cuda_runtime.h>
#include <cuda_bf16.h>
#include <cstdint>
#include <math.h>

#define NPIX 16384        // 128*128
#define NCLASS 5
#define IGNORE_LBL 5
#define MV_BG 4096
#define MV 2048
#define MTOT 12288        // 4096 + 4*2048
#define ANCH_DIM 256

// -------- scratch (device globals; no allocation allowed) --------
__device__ int g_yhat [NPIX];
__device__ int g_order[MTOT];
__device__ int g_ycls [MTOT];
// [hi | lo] layouts, row stride = 2*K
__device__ __nv_bfloat16 g_Xc [MTOT * 1024];   // K=512
__device__ __nv_bfloat16 g_H1c[MTOT * 1024];   // K=512
__device__ __nv_bfloat16 g_H2c[MTOT * 512];    // K=256
__device__ __nv_bfloat16 g_W1c[512 * 1024];
__device__ __nv_bfloat16 g_W2c[256 * 1024];
__device__ __nv_bfloat16 g_W3c[256 * 512];
__device__ float g_H3[MTOT * 256];

// ================= helpers =================
__device__ __forceinline__ uint32_t smem_u32(const void* p) {
    uint32_t a;
    asm("{ .reg .u64 t; cvta.to.shared.u64 t, %1; cvt.u32.u64 %0, t; }" : "=r"(a) : "l"(p));
    return a;
}
__device__ __forceinline__ void cp16(uint32_t dst, const void* src) {
    asm volatile("cp.async.cg.shared.global [%0], [%1], 16;" :: "r"(dst), "l"(src));
}
#define CP_COMMIT() asm volatile("cp.async.commit_group;" ::: "memory")
template <int N> __device__ __forceinline__ void cp_wait() {
    asm volatile("cp.async.wait_group %0;" :: "n"(N) : "memory");
}
__device__ __forceinline__ void ldsm4(uint32_t* r, uint32_t addr) {
    asm volatile("ldmatrix.sync.aligned.m8n8.x4.shared.b16 {%0,%1,%2,%3}, [%4];"
                 : "=r"(r[0]), "=r"(r[1]), "=r"(r[2]), "=r"(r[3]) : "r"(addr));
}
__device__ __forceinline__ void mma16816(float* c, const uint32_t* a, const uint32_t* b) {
    asm volatile(
        "mma.sync.aligned.m16n8k16.row.col.f32.bf16.bf16.f32 "
        "{%0,%1,%2,%3}, {%4,%5,%6,%7}, {%8,%9}, {%0,%1,%2,%3};"
        : "+f"(c[0]), "+f"(c[1]), "+f"(c[2]), "+f"(c[3])
        : "r"(a[0]), "r"(a[1]), "r"(a[2]), "r"(a[3]), "r"(b[0]), "r"(b[1]));
}
__device__ __forceinline__ void split_bf(float v, __nv_bfloat16& hi, __nv_bfloat16& lo) {
    hi = __float2bfloat16(v);
    lo = __float2bfloat16(v - __bfloat162float(hi));
}

// -------- stage 1: strided argmax over labels[0, ::8, ::8, :] --------
__global__ void argmax_kernel(const float* __restrict__ labels) {
    int p = blockIdx.x * blockDim.x + threadIdx.x;
    if (p >= NPIX) return;
    int i = p >> 7, j = p & 127;
    const float* L = labels + (size_t)i * 40960 + (size_t)j * 40;
    float best = L[0];
    int bi = 0;
#pragma unroll
    for (int c = 1; c < NCLASS; c++) {
        float v = L[c];
        if (v > best) { best = v; bi = c; }
    }
    g_yhat[p] = bi;
}

// -------- stage 2: stratified selection per class --------
__global__ void select_kernel(const int* __restrict__ pred) {
    const int c    = blockIdx.x;
    const int mv   = (c == 0) ? MV_BG : MV;
    const int base = (c == 0) ? 0 : MV_BG + (c - 1) * MV;
    const int t = threadIdx.x;            // 512 threads
    const int PPT = NPIX / 512;

    __shared__ int sh[512], se[512];
    __shared__ int s_hk, s_ek, s_nsel;

    const int p0 = t * PPT;
    int lh = 0, le = 0;
    for (int i = 0; i < PPT; i++) {
        int p = p0 + i;
        int m = (g_yhat[p] == c);
        int e = m && (pred[p] == c);
        int h = m && !e;
        lh += h; le += e;
    }
    sh[t] = lh; se[t] = le;
    __syncthreads();
    for (int off = 1; off < 512; off <<= 1) {
        int vh = (t >= off) ? sh[t - off] : 0;
        int ve = (t >= off) ? se[t - off] : 0;
        __syncthreads();
        sh[t] += vh; se[t] += ve;
        __syncthreads();
    }
    const int hoff = sh[t] - lh;
    const int eoff = se[t] - le;
    const int nh = sh[511], ne = se[511];
    if (t == 0) {
        int cnt = nh + ne;
        int n_sel = (cnt > 1) ? min(cnt, mv) : 0;
        int hk;
        if (2 * nh >= n_sel && 2 * ne >= n_sel) hk = n_sel >> 1;
        else if (2 * nh >= n_sel)               hk = n_sel - ne;
        else                                     hk = nh;
        s_hk = hk; s_ek = n_sel - hk; s_nsel = n_sel;
    }
    __syncthreads();
    const int hk = s_hk, ek = s_ek, nsel = s_nsel;

    for (int r = t; r < mv; r += 512) {
        g_ycls[base + r] = (r < nsel) ? c : IGNORE_LBL;
        if (r >= nsel) g_order[base + r] = -1;
    }

    int hr = hoff, er = eoff;
    for (int i = 0; i < PPT; i++) {
        int p = p0 + i;
        if (g_yhat[p] == c) {
            if (pred[p] == c) { if (er < ek) g_order[base + hk + er] = p; er++; }
            else              { if (hr < hk) g_order[base + hr]     = p; hr++; }
        }
    }
}

// -------- stage 3: gather + fp32->bf16 hi/lo split into [hi|lo] layout -----
__global__ void gather_split_kernel(const float* __restrict__ feats) {
    const int rb = blockIdx.x * 8;
    const int t = threadIdx.x;                 // channels 2t, 2t+1
#pragma unroll
    for (int rr = 0; rr < 8; rr++) {
        const int r = rb + rr;
        const int p = g_order[r];
        float v0 = 0.f, v1 = 0.f;
        if (p >= 0) {
            v0 = __ldg(feats + (size_t)(2 * t)     * NPIX + p);
            v1 = __ldg(feats + (size_t)(2 * t + 1) * NPIX + p);
        }
        __nv_bfloat16 h0, l0, h1, l1;
        split_bf(v0, h0, l0);
        split_bf(v1, h1, l1);
        size_t b = (size_t)r * 1024 + 2 * t;
        *(__nv_bfloat162*)(g_Xc + b)       = __halves2bfloat162(h0, h1);
        *(__nv_bfloat162*)(g_Xc + b + 512) = __halves2bfloat162(l0, l1);
    }
}

// -------- weight split: W' = [hi | lo], row stride 2K ----------------------
__global__ void wsplit_kernel(const float* __restrict__ w, __nv_bfloat16* __restrict__ wc,
                              int K, int total) {
    int i = blockIdx.x * 256 + threadIdx.x;
    if (i >= total) return;
    int r = i / K, c = i - r * K;
    __nv_bfloat16 h, l;
    split_bf(w[i], h, l);
    size_t b = (size_t)r * 2 * K + c;
    wc[b]     = h;
    wc[b + K] = l;
}

// -------- stage 4: bf16 mma.sync GEMM with split-K segments ----------------
// C = act( Ah*Wh^T + Ah*Wl^T + Al*Wh^T + bias )
// CTA tile 128x128, BK=32, 4-stage cp.async, 8 warps (4m x 2n), warp 32x64.
// smem per stage: A[128][40] + B[128][40] bf16 = 20480 B; 4 stages = 81920 B.
#define STAGE_B 20480
template <int ACT>
__global__ __launch_bounds__(256, 2) void mma_gemm(
    const __nv_bfloat16* __restrict__ A, const __nv_bfloat16* __restrict__ W,
    const float* __restrict__ bias, int K, int NC,
    __nv_bfloat16* __restrict__ outc, float* __restrict__ outf)
{
    extern __shared__ char smem[];
    const uint32_t sb = smem_u32(smem);
    const int tid = threadIdx.x, lane = tid & 31, wid = tid >> 5;
    const int wm = wid & 3, wn = wid >> 2;
    const int m0 = blockIdx.y * 128, n0 = blockIdx.x * 128;
    const int Nout = gridDim.x * 128;
    const int sA = 2 * K;          // row stride (elems) for both A and W
    const int SC = K / 32;         // chunks per segment

    float acc[2][8][4];
#pragma unroll
    for (int i = 0; i < 2; i++)
#pragma unroll
        for (int j = 0; j < 8; j++)
#pragma unroll
            for (int k = 0; k < 4; k++) acc[i][j][k] = 0.f;

    auto produce = [&](int c) {
        int seg = c / SC;
        int kin = (c - seg * SC) * 32;
        int aOff = (seg == 2) ? K : 0;      // segs: Ah,Ah,Al
        int wOff = (seg == 1) ? K : 0;      // segs: Wh,Wl,Wh
        const __nv_bfloat16* ga = A + (size_t)m0 * sA + aOff + kin;
        const __nv_bfloat16* gw = W + (size_t)n0 * sA + wOff + kin;
        uint32_t s0 = sb + (c & 3) * STAGE_B;
#pragma unroll
        for (int i = 0; i < 2; i++) {
            int id = tid + i * 256;
            int row = id >> 2, c16 = id & 3;
            cp16(s0 + row * 80 + c16 * 16,         ga + (size_t)row * sA + c16 * 8);
            cp16(s0 + 10240 + row * 80 + c16 * 16, gw + (size_t)row * sA + c16 * 8);
        }
        CP_COMMIT();
    };

    produce(0); produce(1); produce(2);

    for (int c = 0; c < NC; c++) {
        cp_wait<2>();
        __syncthreads();
        if (c + 3 < NC) produce(c + 3); else CP_COMMIT();

        uint32_t s0 = sb + (c & 3) * STAGE_B;
#pragma unroll
        for (int s = 0; s < 2; s++) {
            const int ko = s * 16;
            uint32_t af[2][4], bf[4][4];
            {
                int rowA = wm * 32 + (lane & 15);
                int colA = ko + ((lane >> 4) << 3);
                uint32_t base = s0 + rowA * 80 + colA * 2;
                ldsm4(af[0], base);
                ldsm4(af[1], base + 16 * 80);
            }
#pragma unroll
            for (int j2 = 0; j2 < 4; j2++) {
                int rowB = wn * 64 + j2 * 16 + (lane & 7) + (((lane >> 4) & 1) << 3);
                int colB = ko + (((lane >> 3) & 1) << 3);
                ldsm4(bf[j2], s0 + 10240 + rowB * 80 + colB * 2);
            }
#pragma unroll
            for (int i = 0; i < 2; i++)
#pragma unroll
                for (int j2 = 0; j2 < 4; j2++) {
                    mma16816(acc[i][2 * j2],     af[i], bf[j2]);
                    mma16816(acc[i][2 * j2 + 1], af[i], bf[j2] + 2);
                }
        }
    }

    // ---------------- epilogue ----------------
    if (ACT == 1) {
        const int strideO = 2 * Nout;
#pragma unroll
        for (int i = 0; i < 2; i++)
#pragma unroll
            for (int h = 0; h < 2; h++) {
                const int r = m0 + wm * 32 + i * 16 + (lane >> 2) + h * 8;
#pragma unroll
                for (int j = 0; j < 8; j++) {
                    const int n = n0 + wn * 64 + j * 8 + 2 * (lane & 3);
                    float v0 = acc[i][j][2 * h]     + __ldg(bias + n);
                    float v1 = acc[i][j][2 * h + 1] + __ldg(bias + n + 1);
                    v0 = (v0 >= 0.f) ? v0 : 0.2f * v0;
                    v1 = (v1 >= 0.f) ? v1 : 0.2f * v1;
                    __nv_bfloat16 h0, l0, h1, l1;
                    split_bf(v0, h0, l0);
                    split_bf(v1, h1, l1);
                    *(__nv_bfloat162*)(outc + (size_t)r * strideO + n) =
                        __halves2bfloat162(h0, h1);
                    *(__nv_bfloat162*)(outc + (size_t)r * strideO + Nout + n) =
                        __halves2bfloat162(l0, l1);
                }
            }
    } else {
#pragma unroll
        for (int i = 0; i < 2; i++)
#pragma unroll
            for (int h = 0; h < 2; h++) {
                const int r = m0 + wm * 32 + i * 16 + (lane >> 2) + h * 8;
#pragma unroll
                for (int j = 0; j < 8; j++) {
                    const int n = n0 + wn * 64 + j * 8 + 2 * (lane & 3);
                    float v0 = acc[i][j][2 * h]     + __ldg(bias + n);
                    float v1 = acc[i][j][2 * h + 1] + __ldg(bias + n + 1);
                    *(float2*)(outf + (size_t)r * Nout + n) = make_float2(v0, v1);
                }
            }
    }
}

// -------- stage 5: row L2-normalize + emit y_ as float --------------------
__global__ void norm_kernel(float* __restrict__ out, int out_size) {
    const int warp = threadIdx.x >> 5, lane = threadIdx.x & 31;
    const int r = blockIdx.x * 8 + warp;
    if (r >= MTOT) return;
    const float4* row = (const float4*)(g_H3 + (size_t)r * 256);
    float4 v0 = row[lane * 2], v1 = row[lane * 2 + 1];
    float ss = v0.x * v0.x + v0.y * v0.y + v0.z * v0.z + v0.w * v0.w
             + v1.x * v1.x + v1.y * v1.y + v1.z * v1.z + v1.w * v1.w;
#pragma unroll
    for (int o = 16; o; o >>= 1) ss += __shfl_xor_sync(0xffffffffu, ss, o);
    float inv = 1.0f / fmaxf(sqrtf(ss), 1e-12f);
    v0.x *= inv; v0.y *= inv; v0.z *= inv; v0.w *= inv;
    v1.x *= inv; v1.y *= inv; v1.z *= inv; v1.w *= inv;
    float4* orow = (float4*)(out + (size_t)r * 256);
    orow[lane * 2]     = v0;
    orow[lane * 2 + 1] = v1;
    if (lane == 0 && out_size >= MTOT * ANCH_DIM + MTOT)
        out[MTOT * ANCH_DIM + r] = (float)g_ycls[r];
}

// ---------------------------------------------------------------------------
extern "C" void kernel_launch(void* const* d_in, const int* in_sizes, int n_in,
                              void* d_out, int out_size)
{
    const float* feats    = (const float*)d_in[0];
    const float* labels   = (const float*)d_in[1];
    const int*   predicts = (const int*)  d_in[2];
    const float* w1 = (const float*)d_in[3];
    const float* b1 = (const float*)d_in[4];
    const float* w2 = (const float*)d_in[5];
    const float* b2 = (const float*)d_in[6];
    const float* w3 = (const float*)d_in[7];
    const float* b3 = (const float*)d_in[8];
    float* out = (float*)d_out;

    cudaFuncSetAttribute(mma_gemm<1>, cudaFuncAttributeMaxDynamicSharedMemorySize, 4 * STAGE_B);
    cudaFuncSetAttribute(mma_gemm<0>, cudaFuncAttributeMaxDynamicSharedMemorySize, 4 * STAGE_B);

    __nv_bfloat16 *Xc, *H1c, *H2c, *W1c, *W2c, *W3c;
    cudaGetSymbolAddress((void**)&Xc,  g_Xc);
    cudaGetSymbolAddress((void**)&H1c, g_H1c);
    cudaGetSymbolAddress((void**)&H2c, g_H2c);
    cudaGetSymbolAddress((void**)&W1c, g_W1c);
    cudaGetSymbolAddress((void**)&W2c, g_W2c);
    cudaGetSymbolAddress((void**)&W3c, g_W3c);
    float* H3;
    cudaGetSymbolAddress((void**)&H3, g_H3);

    argmax_kernel<<<NPIX / 256, 256>>>(labels);
    select_kernel<<<NCLASS, 512>>>(predicts);
    gather_split_kernel<<<MTOT / 8, 256>>>(feats);
    wsplit_kernel<<<(512 * 512 + 255) / 256, 256>>>(w1, W1c, 512, 512 * 512);
    wsplit_kernel<<<(256 * 512 + 255) / 256, 256>>>(w2, W2c, 512, 256 * 512);
    wsplit_kernel<<<(256 * 256 + 255) / 256, 256>>>(w3, W3c, 256, 256 * 256);

    // layer 1: [12288,512] -> [12288,512], leaky, split store
    mma_gemm<1><<<dim3(4, 96), 256, 4 * STAGE_B>>>(Xc,  W1c, b1, 512, 48, H1c, nullptr);
    // layer 2: [12288,512] -> [12288,256], leaky, split store
    mma_gemm<1><<<dim3(2, 96), 256, 4 * STAGE_B>>>(H1c, W2c, b2, 512, 48, H2c, nullptr);
    // layer 3: [12288,256] -> [12288,256], linear, fp32 store
    mma_gemm<0><<<dim3(2, 96), 256, 4 * STAGE_B>>>(H2c, W3c, b3, 256, 24, nullptr, H3);

    norm_kernel<<<MTOT / 8, 256>>>(out, out_size);
}

// round 10
// speedup vs baseline: 1.8528x; 1.0444x over previous
#include <cuda_runtime.h>
#include <cuda_bf16.h>
#include <cstdint>
#include <math.h>

#define NPIX 16384        // 128*128
#define NCLASS 5
#define IGNORE_LBL 5
#define MV_BG 4096
#define MV 2048
#define MTOT 12288        // 4096 + 4*2048
#define ANCH_DIM 256

// -------- scratch (device globals; no allocation allowed) --------
__device__ int g_yhat [NPIX];
__device__ int g_order[MTOT];
__device__ int g_ycls [MTOT];
// [hi | lo] layouts, row stride = 2*K
__device__ __nv_bfloat16 g_Xc [MTOT * 1024];   // K=512
__device__ __nv_bfloat16 g_H1c[MTOT * 1024];   // K=512
__device__ __nv_bfloat16 g_H2c[MTOT * 512];    // K=256
__device__ __nv_bfloat16 g_W1c[512 * 1024];
__device__ __nv_bfloat16 g_W2c[256 * 1024];
__device__ __nv_bfloat16 g_W3c[256 * 512];
__device__ float g_H3[MTOT * 256];

// ================= helpers =================
__device__ __forceinline__ uint32_t smem_u32(const void* p) {
    uint32_t a;
    asm("{ .reg .u64 t; cvta.to.shared.u64 t, %1; cvt.u32.u64 %0, t; }" : "=r"(a) : "l"(p));
    return a;
}
__device__ __forceinline__ void cp16(uint32_t dst, const void* src) {
    asm volatile("cp.async.cg.shared.global [%0], [%1], 16;" :: "r"(dst), "l"(src));
}
#define CP_COMMIT() asm volatile("cp.async.commit_group;" ::: "memory")
template <int N> __device__ __forceinline__ void cp_wait() {
    asm volatile("cp.async.wait_group %0;" :: "n"(N) : "memory");
}
__device__ __forceinline__ void ldsm4(uint32_t* r, uint32_t addr) {
    asm volatile("ldmatrix.sync.aligned.m8n8.x4.shared.b16 {%0,%1,%2,%3}, [%4];"
                 : "=r"(r[0]), "=r"(r[1]), "=r"(r[2]), "=r"(r[3]) : "r"(addr));
}
__device__ __forceinline__ void mma16816(float* c, const uint32_t* a, const uint32_t* b) {
    asm volatile(
        "mma.sync.aligned.m16n8k16.row.col.f32.bf16.bf16.f32 "
        "{%0,%1,%2,%3}, {%4,%5,%6,%7}, {%8,%9}, {%0,%1,%2,%3};"
        : "+f"(c[0]), "+f"(c[1]), "+f"(c[2]), "+f"(c[3])
        : "r"(a[0]), "r"(a[1]), "r"(a[2]), "r"(a[3]), "r"(b[0]), "r"(b[1]));
}
__device__ __forceinline__ void split_bf(float v, __nv_bfloat16& hi, __nv_bfloat16& lo) {
    hi = __float2bfloat16(v);
    lo = __float2bfloat16(v - __bfloat162float(hi));
}

// -------- stage 1: strided argmax over labels[0, ::8, ::8, :] --------
__global__ void argmax_kernel(const float* __restrict__ labels) {
    int p = blockIdx.x * blockDim.x + threadIdx.x;
    if (p >= NPIX) return;
    int i = p >> 7, j = p & 127;
    const float* L = labels + (size_t)i * 40960 + (size_t)j * 40;
    float best = L[0];
    int bi = 0;
#pragma unroll
    for (int c = 1; c < NCLASS; c++) {
        float v = L[c];
        if (v > best) { best = v; bi = c; }
    }
    g_yhat[p] = bi;
}

// -------- stage 2: stratified selection per class --------
__global__ void select_kernel(const int* __restrict__ pred) {
    const int c    = blockIdx.x;
    const int mv   = (c == 0) ? MV_BG : MV;
    const int base = (c == 0) ? 0 : MV_BG + (c - 1) * MV;
    const int t = threadIdx.x;            // 512 threads
    const int PPT = NPIX / 512;

    __shared__ int sh[512], se[512];
    __shared__ int s_hk, s_ek, s_nsel;

    const int p0 = t * PPT;
    int lh = 0, le = 0;
    for (int i = 0; i < PPT; i++) {
        int p = p0 + i;
        int m = (g_yhat[p] == c);
        int e = m && (pred[p] == c);
        int h = m && !e;
        lh += h; le += e;
    }
    sh[t] = lh; se[t] = le;
    __syncthreads();
    for (int off = 1; off < 512; off <<= 1) {
        int vh = (t >= off) ? sh[t - off] : 0;
        int ve = (t >= off) ? se[t - off] : 0;
        __syncthreads();
        sh[t] += vh; se[t] += ve;
        __syncthreads();
    }
    const int hoff = sh[t] - lh;
    const int eoff = se[t] - le;
    const int nh = sh[511], ne = se[511];
    if (t == 0) {
        int cnt = nh + ne;
        int n_sel = (cnt > 1) ? min(cnt, mv) : 0;
        int hk;
        if (2 * nh >= n_sel && 2 * ne >= n_sel) hk = n_sel >> 1;
        else if (2 * nh >= n_sel)               hk = n_sel - ne;
        else                                     hk = nh;
        s_hk = hk; s_ek = n_sel - hk; s_nsel = n_sel;
    }
    __syncthreads();
    const int hk = s_hk, ek = s_ek, nsel = s_nsel;

    for (int r = t; r < mv; r += 512) {
        g_ycls[base + r] = (r < nsel) ? c : IGNORE_LBL;
        if (r >= nsel) g_order[base + r] = -1;
    }

    int hr = hoff, er = eoff;
    for (int i = 0; i < PPT; i++) {
        int p = p0 + i;
        if (g_yhat[p] == c) {
            if (pred[p] == c) { if (er < ek) g_order[base + hk + er] = p; er++; }
            else              { if (hr < hk) g_order[base + hr]     = p; hr++; }
        }
    }
}

// -------- stage 3: gather + fp32->bf16 hi/lo split into [hi|lo] layout -----
__global__ void gather_split_kernel(const float* __restrict__ feats) {
    const int rb = blockIdx.x * 8;
    const int t = threadIdx.x;                 // channels 2t, 2t+1
#pragma unroll
    for (int rr = 0; rr < 8; rr++) {
        const int r = rb + rr;
        const int p = g_order[r];
        float v0 = 0.f, v1 = 0.f;
        if (p >= 0) {
            v0 = __ldg(feats + (size_t)(2 * t)     * NPIX + p);
            v1 = __ldg(feats + (size_t)(2 * t + 1) * NPIX + p);
        }
        __nv_bfloat16 h0, l0, h1, l1;
        split_bf(v0, h0, l0);
        split_bf(v1, h1, l1);
        size_t b = (size_t)r * 1024 + 2 * t;
        *(__nv_bfloat162*)(g_Xc + b)       = __halves2bfloat162(h0, h1);
        *(__nv_bfloat162*)(g_Xc + b + 512) = __halves2bfloat162(l0, l1);
    }
}

// -------- weight split for all 3 layers in one launch ----------------------
__global__ void wsplit_all(const float* __restrict__ w1, const float* __restrict__ w2,
                           const float* __restrict__ w3) {
    int i = blockIdx.x * 256 + threadIdx.x;
    const float* w;
    __nv_bfloat16* wc;
    int K;
    if (i < 262144)       { w = w1; wc = g_W1c; K = 512; }
    else if (i < 393216)  { i -= 262144; w = w2; wc = g_W2c; K = 512; }
    else if (i < 458752)  { i -= 393216; w = w3; wc = g_W3c; K = 256; }
    else return;
    int r = i / K, c = i - r * K;
    __nv_bfloat16 h, l;
    split_bf(w[i], h, l);
    size_t b = (size_t)r * 2 * K + c;
    wc[b]     = h;
    wc[b + K] = l;
}

// -------- stage 4: bf16 mma.sync GEMM with split-K segments ----------------
// C = act( Ah*Wh^T + Ah*Wl^T + Al*Wh^T + bias )
// CTA tile 128x64, BK=32, 4-stage cp.async, 8 warps (4m x 2n), warp 32x32.
// smem/stage: A 128*80 + B 64*80 = 15360 B; 4 stages = 61440 B -> 3 CTAs/SM.
#define STAGE_B 15360
template <int ACT>
__global__ __launch_bounds__(256, 3) void mma_gemm(
    const __nv_bfloat16* __restrict__ A, const __nv_bfloat16* __restrict__ W,
    const float* __restrict__ bias, int K, int NC,
    __nv_bfloat16* __restrict__ outc, float* __restrict__ outf)
{
    extern __shared__ char smem[];
    const uint32_t sb = smem_u32(smem);
    const int tid = threadIdx.x, lane = tid & 31, wid = tid >> 5;
    const int wm = wid & 3, wn = wid >> 2;
    const int m0 = blockIdx.y * 128, n0 = blockIdx.x * 64;
    const int Nout = gridDim.x * 64;
    const int sA = 2 * K;          // row stride (elems) for both A and W
    const int SC = K / 32;         // chunks per segment

    float acc[2][4][4];
#pragma unroll
    for (int i = 0; i < 2; i++)
#pragma unroll
        for (int j = 0; j < 4; j++)
#pragma unroll
            for (int k = 0; k < 4; k++) acc[i][j][k] = 0.f;

    auto produce = [&](int c) {
        int seg = c / SC;
        int kin = (c - seg * SC) * 32;
        int aOff = (seg == 2) ? K : 0;      // segs: Ah,Ah,Al
        int wOff = (seg == 1) ? K : 0;      // segs: Wh,Wl,Wh
        const __nv_bfloat16* ga = A + (size_t)m0 * sA + aOff + kin;
        const __nv_bfloat16* gw = W + (size_t)n0 * sA + wOff + kin;
        uint32_t s0 = sb + (c & 3) * STAGE_B;
#pragma unroll
        for (int i = 0; i < 2; i++) {       // A: 128 rows x 4 chunks of 16B
            int id = tid + i * 256;
            int row = id >> 2, c16 = id & 3;
            cp16(s0 + row * 80 + c16 * 16, ga + (size_t)row * sA + c16 * 8);
        }
        {                                   // B: 64 rows x 4 chunks of 16B
            int row = tid >> 2, c16 = tid & 3;
            cp16(s0 + 10240 + row * 80 + c16 * 16, gw + (size_t)row * sA + c16 * 8);
        }
        CP_COMMIT();
    };

    produce(0); produce(1); produce(2);

    for (int c = 0; c < NC; c++) {
        cp_wait<2>();
        __syncthreads();
        if (c + 3 < NC) produce(c + 3); else CP_COMMIT();

        uint32_t s0 = sb + (c & 3) * STAGE_B;
#pragma unroll
        for (int s = 0; s < 2; s++) {
            const int ko = s * 16;
            uint32_t af[2][4], bf[2][4];
            {
                int rowA = wm * 32 + (lane & 15);
                int colA = ko + ((lane >> 4) << 3);
                uint32_t base = s0 + rowA * 80 + colA * 2;
                ldsm4(af[0], base);
                ldsm4(af[1], base + 16 * 80);
            }
#pragma unroll
            for (int j2 = 0; j2 < 2; j2++) {
                int rowB = wn * 32 + j2 * 16 + (lane & 7) + (((lane >> 4) & 1) << 3);
                int colB = ko + (((lane >> 3) & 1) << 3);
                ldsm4(bf[j2], s0 + 10240 + rowB * 80 + colB * 2);
            }
#pragma unroll
            for (int i = 0; i < 2; i++)
#pragma unroll
                for (int j2 = 0; j2 < 2; j2++) {
                    mma16816(acc[i][2 * j2],     af[i], bf[j2]);
                    mma16816(acc[i][2 * j2 + 1], af[i], bf[j2] + 2);
                }
        }
    }

    // ---------------- epilogue ----------------
    if (ACT == 1) {
        const int strideO = 2 * Nout;
#pragma unroll
        for (int i = 0; i < 2; i++)
#pragma unroll
            for (int h = 0; h < 2; h++) {
                const int r = m0 + wm * 32 + i * 16 + (lane >> 2) + h * 8;
#pragma unroll
                for (int j = 0; j < 4; j++) {
                    const int n = n0 + wn * 32 + j * 8 + 2 * (lane & 3);
                    float v0 = acc[i][j][2 * h]     + __ldg(bias + n);
                    float v1 = acc[i][j][2 * h + 1] + __ldg(bias + n + 1);
                    v0 = (v0 >= 0.f) ? v0 : 0.2f * v0;
                    v1 = (v1 >= 0.f) ? v1 : 0.2f * v1;
                    __nv_bfloat16 h0, l0, h1, l1;
                    split_bf(v0, h0, l0);
                    split_bf(v1, h1, l1);
                    *(__nv_bfloat162*)(outc + (size_t)r * strideO + n) =
                        __halves2bfloat162(h0, h1);
                    *(__nv_bfloat162*)(outc + (size_t)r * strideO + Nout + n) =
                        __halves2bfloat162(l0, l1);
                }
            }
    } else {
#pragma unroll
        for (int i = 0; i < 2; i++)
#pragma unroll
            for (int h = 0; h < 2; h++) {
                const int r = m0 + wm * 32 + i * 16 + (lane >> 2) + h * 8;
#pragma unroll
                for (int j = 0; j < 4; j++) {
                    const int n = n0 + wn * 32 + j * 8 + 2 * (lane & 3);
                    float v0 = acc[i][j][2 * h]     + __ldg(bias + n);
                    float v1 = acc[i][j][2 * h + 1] + __ldg(bias + n + 1);
                    *(float2*)(outf + (size_t)r * Nout + n) = make_float2(v0, v1);
                }
            }
    }
}

// -------- stage 5: row L2-normalize + emit y_ as float --------------------
__global__ void norm_kernel(float* __restrict__ out, int out_size) {
    const int warp = threadIdx.x >> 5, lane = threadIdx.x & 31;
    const int r = blockIdx.x * 8 + warp;
    if (r >= MTOT) return;
    const float4* row = (const float4*)(g_H3 + (size_t)r * 256);
    float4 v0 = row[lane * 2], v1 = row[lane * 2 + 1];
    float ss = v0.x * v0.x + v0.y * v0.y + v0.z * v0.z + v0.w * v0.w
             + v1.x * v1.x + v1.y * v1.y + v1.z * v1.z + v1.w * v1.w;
#pragma unroll
    for (int o = 16; o; o >>= 1) ss += __shfl_xor_sync(0xffffffffu, ss, o);
    float inv = 1.0f / fmaxf(sqrtf(ss), 1e-12f);
    v0.x *= inv; v0.y *= inv; v0.z *= inv; v0.w *= inv;
    v1.x *= inv; v1.y *= inv; v1.z *= inv; v1.w *= inv;
    float4* orow = (float4*)(out + (size_t)r * 256);
    orow[lane * 2]     = v0;
    orow[lane * 2 + 1] = v1;
    if (lane == 0 && out_size >= MTOT * ANCH_DIM + MTOT)
        out[MTOT * ANCH_DIM + r] = (float)g_ycls[r];
}

// ---------------------------------------------------------------------------
extern "C" void kernel_launch(void* const* d_in, const int* in_sizes, int n_in,
                              void* d_out, int out_size)
{
    const float* feats    = (const float*)d_in[0];
    const float* labels   = (const float*)d_in[1];
    const int*   predicts = (const int*)  d_in[2];
    const float* w1 = (const float*)d_in[3];
    const float* b1 = (const float*)d_in[4];
    const float* w2 = (const float*)d_in[5];
    const float* b2 = (const float*)d_in[6];
    const float* w3 = (const float*)d_in[7];
    const float* b3 = (const float*)d_in[8];
    float* out = (float*)d_out;

    cudaFuncSetAttribute(mma_gemm<1>, cudaFuncAttributeMaxDynamicSharedMemorySize, 4 * STAGE_B);
    cudaFuncSetAttribute(mma_gemm<0>, cudaFuncAttributeMaxDynamicSharedMemorySize, 4 * STAGE_B);

    __nv_bfloat16 *Xc, *H1c, *H2c, *W1c, *W2c, *W3c;
    cudaGetSymbolAddress((void**)&Xc,  g_Xc);
    cudaGetSymbolAddress((void**)&H1c, g_H1c);
    cudaGetSymbolAddress((void**)&H2c, g_H2c);
    cudaGetSymbolAddress((void**)&W1c, g_W1c);
    cudaGetSymbolAddress((void**)&W2c, g_W2c);
    cudaGetSymbolAddress((void**)&W3c, g_W3c);
    float* H3;
    cudaGetSymbolAddress((void**)&H3, g_H3);

    argmax_kernel<<<NPIX / 256, 256>>>(labels);
    select_kernel<<<NCLASS, 512>>>(predicts);
    gather_split_kernel<<<MTOT / 8, 256>>>(feats);
    wsplit_all<<<1792, 256>>>(w1, w2, w3);

    // layer 1: [12288,512] -> [12288,512], leaky, split store
    mma_gemm<1><<<dim3(8, 96), 256, 4 * STAGE_B>>>(Xc,  W1c, b1, 512, 48, H1c, nullptr);
    // layer 2: [12288,512] -> [12288,256], leaky, split store
    mma_gemm<1><<<dim3(4, 96), 256, 4 * STAGE_B>>>(H1c, W2c, b2, 512, 48, H2c, nullptr);
    // layer 3: [12288,256] -> [12288,256], linear, fp32 store
    mma_gemm<0><<<dim3(4, 96), 256, 4 * STAGE_B>>>(H2c, W3c, b3, 256, 24, nullptr, H3);

    norm_kernel<<<MTOT / 8, 256>>>(out, out_size);
}

// round 15
// speedup vs baseline: 2.1382x; 1.1540x over previous
#include <cuda_runtime.h>
#include <cuda_bf16.h>
#include <cstdint>
#include <math.h>

#define NPIX 16384        // 128*128
#define NCLASS 5
#define IGNORE_LBL 5
#define MV_BG 4096
#define MV 2048
#define MTOT 12288        // 4096 + 4*2048
#define ANCH_DIM 256

// -------- scratch (device globals; no allocation allowed) --------
__device__ int g_yhat [NPIX];
__device__ int g_order[MTOT];
__device__ int g_ycls [MTOT];
// [hi | lo] layouts, row stride = 2*K
__device__ __nv_bfloat16 g_Xc [MTOT * 1024];   // K=512
__device__ __nv_bfloat16 g_H1c[MTOT * 1024];   // K=512
__device__ __nv_bfloat16 g_H2c[MTOT * 512];    // K=256
__device__ __nv_bfloat16 g_W1c[512 * 1024];
__device__ __nv_bfloat16 g_W2c[256 * 1024];
__device__ __nv_bfloat16 g_W3c[256 * 512];
__device__ float g_H3[MTOT * 256];

// ================= helpers =================
__device__ __forceinline__ uint32_t smem_u32(const void* p) {
    uint32_t a;
    asm("{ .reg .u64 t; cvta.to.shared.u64 t, %1; cvt.u32.u64 %0, t; }" : "=r"(a) : "l"(p));
    return a;
}
__device__ __forceinline__ void cp16(uint32_t dst, const void* src) {
    asm volatile("cp.async.cg.shared.global [%0], [%1], 16;" :: "r"(dst), "l"(src));
}
#define CP_COMMIT() asm volatile("cp.async.commit_group;" ::: "memory")
template <int N> __device__ __forceinline__ void cp_wait() {
    asm volatile("cp.async.wait_group %0;" :: "n"(N) : "memory");
}
__device__ __forceinline__ void ldsm4(uint32_t* r, uint32_t addr) {
    asm volatile("ldmatrix.sync.aligned.m8n8.x4.shared.b16 {%0,%1,%2,%3}, [%4];"
                 : "=r"(r[0]), "=r"(r[1]), "=r"(r[2]), "=r"(r[3]) : "r"(addr));
}
__device__ __forceinline__ void mma16816(float* c, const uint32_t* a, const uint32_t* b) {
    asm volatile(
        "mma.sync.aligned.m16n8k16.row.col.f32.bf16.bf16.f32 "
        "{%0,%1,%2,%3}, {%4,%5,%6,%7}, {%8,%9}, {%0,%1,%2,%3};"
        : "+f"(c[0]), "+f"(c[1]), "+f"(c[2]), "+f"(c[3])
        : "r"(a[0]), "r"(a[1]), "r"(a[2]), "r"(a[3]), "r"(b[0]), "r"(b[1]));
}
__device__ __forceinline__ void split_bf(float v, __nv_bfloat16& hi, __nv_bfloat16& lo) {
    hi = __float2bfloat16(v);
    lo = __float2bfloat16(v - __bfloat162float(hi));
}

// -------- stage 1: strided argmax over labels[0, ::8, ::8, :] --------
__global__ void argmax_kernel(const float* __restrict__ labels) {
    int p = blockIdx.x * blockDim.x + threadIdx.x;
    if (p >= NPIX) return;
    int i = p >> 7, j = p & 127;
    const float* L = labels + (size_t)i * 40960 + (size_t)j * 40;
    float best = L[0];
    int bi = 0;
#pragma unroll
    for (int c = 1; c < NCLASS; c++) {
        float v = L[c];
        if (v > best) { best = v; bi = c; }
    }
    g_yhat[p] = bi;
}

// -------- stage 2: stratified selection per class --------
__global__ void select_kernel(const int* __restrict__ pred) {
    const int c    = blockIdx.x;
    const int mv   = (c == 0) ? MV_BG : MV;
    const int base = (c == 0) ? 0 : MV_BG + (c - 1) * MV;
    const int t = threadIdx.x;            // 512 threads
    const int PPT = NPIX / 512;

    __shared__ int sh[512], se[512];
    __shared__ int s_hk, s_ek, s_nsel;

    const int p0 = t * PPT;
    int lh = 0, le = 0;
    for (int i = 0; i < PPT; i++) {
        int p = p0 + i;
        int m = (g_yhat[p] == c);
        int e = m && (pred[p] == c);
        int h = m && !e;
        lh += h; le += e;
    }
    sh[t] = lh; se[t] = le;
    __syncthreads();
    for (int off = 1; off < 512; off <<= 1) {
        int vh = (t >= off) ? sh[t - off] : 0;
        int ve = (t >= off) ? se[t - off] : 0;
        __syncthreads();
        sh[t] += vh; se[t] += ve;
        __syncthreads();
    }
    const int hoff = sh[t] - lh;
    const int eoff = se[t] - le;
    const int nh = sh[511], ne = se[511];
    if (t == 0) {
        int cnt = nh + ne;
        int n_sel = (cnt > 1) ? min(cnt, mv) : 0;
        int hk;
        if (2 * nh >= n_sel && 2 * ne >= n_sel) hk = n_sel >> 1;
        else if (2 * nh >= n_sel)               hk = n_sel - ne;
        else                                     hk = nh;
        s_hk = hk; s_ek = n_sel - hk; s_nsel = n_sel;
    }
    __syncthreads();
    const int hk = s_hk, ek = s_ek, nsel = s_nsel;

    for (int r = t; r < mv; r += 512) {
        g_ycls[base + r] = (r < nsel) ? c : IGNORE_LBL;
        if (r >= nsel) g_order[base + r] = -1;
    }

    int hr = hoff, er = eoff;
    for (int i = 0; i < PPT; i++) {
        int p = p0 + i;
        if (g_yhat[p] == c) {
            if (pred[p] == c) { if (er < ek) g_order[base + hk + er] = p; er++; }
            else              { if (hr < hk) g_order[base + hr]     = p; hr++; }
        }
    }
}

// -------- stage 3: gather + fp32->bf16 hi/lo split into [hi|lo] layout -----
__global__ void gather_split_kernel(const float* __restrict__ feats) {
    const int rb = blockIdx.x * 8;
    const int t = threadIdx.x;                 // channels 2t, 2t+1
#pragma unroll
    for (int rr = 0; rr < 8; rr++) {
        const int r = rb + rr;
        const int p = g_order[r];
        float v0 = 0.f, v1 = 0.f;
        if (p >= 0) {
            v0 = __ldg(feats + (size_t)(2 * t)     * NPIX + p);
            v1 = __ldg(feats + (size_t)(2 * t + 1) * NPIX + p);
        }
        __nv_bfloat16 h0, l0, h1, l1;
        split_bf(v0, h0, l0);
        split_bf(v1, h1, l1);
        size_t b = (size_t)r * 1024 + 2 * t;
        *(__nv_bfloat162*)(g_Xc + b)       = __halves2bfloat162(h0, h1);
        *(__nv_bfloat162*)(g_Xc + b + 512) = __halves2bfloat162(l0, l1);
    }
}

// -------- weight split for all 3 layers in one launch ----------------------
__global__ void wsplit_all(const float* __restrict__ w1, const float* __restrict__ w2,
                           const float* __restrict__ w3) {
    int i = blockIdx.x * 256 + threadIdx.x;
    const float* w;
    __nv_bfloat16* wc;
    int K;
    if (i < 262144)       { w = w1; wc = g_W1c; K = 512; }
    else if (i < 393216)  { i -= 262144; w = w2; wc = g_W2c; K = 512; }
    else if (i < 458752)  { i -= 393216; w = w3; wc = g_W3c; K = 256; }
    else return;
    int r = i / K, c = i - r * K;
    __nv_bfloat16 h, l;
    split_bf(w[i], h, l);
    size_t b = (size_t)r * 2 * K + c;
    wc[b]     = h;
    wc[b + K] = l;
}

// -------- stage 4: bf16 mma.sync GEMM, fused hi/lo per K-window ------------
// Per 32-K window, load Ah, Al, Wh, Wl once; compute Ah*Wh + Ah*Wl + Al*Wh.
// CTA tile 128x64, 2-stage cp.async, 8 warps (4m x 2n), warp 32x32.
// Stage: Ah 128*80 + Al 128*80 + Wh 64*80 + Wl 64*80 = 30720 B; x2 = 61440 B.
#define STAGE_B 30720
#define OFF_AL 10240
#define OFF_WH 20480
#define OFF_WL 25600
template <int ACT>
__global__ __launch_bounds__(256, 3) void mma_gemm(
    const __nv_bfloat16* __restrict__ A, const __nv_bfloat16* __restrict__ W,
    const float* __restrict__ bias, int K, int NW,
    __nv_bfloat16* __restrict__ outc, float* __restrict__ outf)
{
    extern __shared__ char smem[];
    const uint32_t sb = smem_u32(smem);
    const int tid = threadIdx.x, lane = tid & 31, wid = tid >> 5;
    const int wm = wid & 3, wn = wid >> 2;
    const int m0 = blockIdx.y * 128, n0 = blockIdx.x * 64;
    const int Nout = gridDim.x * 64;
    const int sA = 2 * K;          // row stride (elems) for both A and W

    float acc[2][4][4];
#pragma unroll
    for (int i = 0; i < 2; i++)
#pragma unroll
        for (int j = 0; j < 4; j++)
#pragma unroll
            for (int k = 0; k < 4; k++) acc[i][j][k] = 0.f;

    auto produce = [&](int w) {
        const __nv_bfloat16* ga = A + (size_t)m0 * sA + w * 32;
        const __nv_bfloat16* gw = W + (size_t)n0 * sA + w * 32;
        uint32_t s0 = sb + (w & 1) * STAGE_B;
#pragma unroll
        for (int i = 0; i < 2; i++) {       // Ah + Al: 128 rows x 4 chunks
            int id = tid + i * 256;
            int row = id >> 2, c16 = id & 3;
            const __nv_bfloat16* gr = ga + (size_t)row * sA + c16 * 8;
            cp16(s0 + row * 80 + c16 * 16,          gr);
            cp16(s0 + OFF_AL + row * 80 + c16 * 16, gr + K);
        }
        {                                   // Wh + Wl: 64 rows x 4 chunks
            int row = tid >> 2, c16 = tid & 3;
            const __nv_bfloat16* gr = gw + (size_t)row * sA + c16 * 8;
            cp16(s0 + OFF_WH + row * 80 + c16 * 16, gr);
            cp16(s0 + OFF_WL + row * 80 + c16 * 16, gr + K);
        }
        CP_COMMIT();
    };

    produce(0);
    produce(1);

    for (int w = 0; w < NW; w++) {
        cp_wait<1>();
        __syncthreads();
        uint32_t s0 = sb + (w & 1) * STAGE_B;

#pragma unroll
        for (int s = 0; s < 2; s++) {
            const int ko = s * 16;
            uint32_t bh[2][4], bl[2][4], a[2][4];
#pragma unroll
            for (int j2 = 0; j2 < 2; j2++) {
                int rowB = wn * 32 + j2 * 16 + (lane & 7) + (((lane >> 4) & 1) << 3);
                int colB = ko + (((lane >> 3) & 1) << 3);
                uint32_t bo = rowB * 80 + colB * 2;
                ldsm4(bh[j2], s0 + OFF_WH + bo);
                ldsm4(bl[j2], s0 + OFF_WL + bo);
            }
            const int rowA = wm * 32 + (lane & 15);
            const int colA = ko + ((lane >> 4) << 3);
            const uint32_t ao = rowA * 80 + colA * 2;
            // A-hi x (W-hi, W-lo)
            ldsm4(a[0], s0 + ao);
            ldsm4(a[1], s0 + ao + 16 * 80);
#pragma unroll
            for (int i = 0; i < 2; i++)
#pragma unroll
                for (int j2 = 0; j2 < 2; j2++) {
                    mma16816(acc[i][2 * j2],     a[i], bh[j2]);
                    mma16816(acc[i][2 * j2 + 1], a[i], bh[j2] + 2);
                    mma16816(acc[i][2 * j2],     a[i], bl[j2]);
                    mma16816(acc[i][2 * j2 + 1], a[i], bl[j2] + 2);
                }
            // A-lo x W-hi
            ldsm4(a[0], s0 + OFF_AL + ao);
            ldsm4(a[1], s0 + OFF_AL + ao + 16 * 80);
#pragma unroll
            for (int i = 0; i < 2; i++)
#pragma unroll
                for (int j2 = 0; j2 < 2; j2++) {
                    mma16816(acc[i][2 * j2],     a[i], bh[j2]);
                    mma16816(acc[i][2 * j2 + 1], a[i], bh[j2] + 2);
                }
        }

        __syncthreads();                    // all reads done before refill
        if (w + 2 < NW) produce(w + 2);
    }

    // ---------------- epilogue ----------------
    if (ACT == 1) {
        const int strideO = 2 * Nout;
#pragma unroll
        for (int i = 0; i < 2; i++)
#pragma unroll
            for (int h = 0; h < 2; h++) {
                const int r = m0 + wm * 32 + i * 16 + (lane >> 2) + h * 8;
#pragma unroll
                for (int j = 0; j < 4; j++) {
                    const int n = n0 + wn * 32 + j * 8 + 2 * (lane & 3);
                    float v0 = acc[i][j][2 * h]     + __ldg(bias + n);
                    float v1 = acc[i][j][2 * h + 1] + __ldg(bias + n + 1);
                    v0 = (v0 >= 0.f) ? v0 : 0.2f * v0;
                    v1 = (v1 >= 0.f) ? v1 : 0.2f * v1;
                    __nv_bfloat16 h0, l0, h1, l1;
                    split_bf(v0, h0, l0);
                    split_bf(v1, h1, l1);
                    *(__nv_bfloat162*)(outc + (size_t)r * strideO + n) =
                        __halves2bfloat162(h0, h1);
                    *(__nv_bfloat162*)(outc + (size_t)r * strideO + Nout + n) =
                        __halves2bfloat162(l0, l1);
                }
            }
    } else {
#pragma unroll
        for (int i = 0; i < 2; i++)
#pragma unroll
            for (int h = 0; h < 2; h++) {
                const int r = m0 + wm * 32 + i * 16 + (lane >> 2) + h * 8;
#pragma unroll
                for (int j = 0; j < 4; j++) {
                    const int n = n0 + wn * 32 + j * 8 + 2 * (lane & 3);
                    float v0 = acc[i][j][2 * h]     + __ldg(bias + n);
                    float v1 = acc[i][j][2 * h + 1] + __ldg(bias + n + 1);
                    *(float2*)(outf + (size_t)r * Nout + n) = make_float2(v0, v1);
                }
            }
    }
}

// -------- stage 5: row L2-normalize + emit y_ as float --------------------
__global__ void norm_kernel(float* __restrict__ out, int out_size) {
    const int warp = threadIdx.x >> 5, lane = threadIdx.x & 31;
    const int r = blockIdx.x * 8 + warp;
    if (r >= MTOT) return;
    const float4* row = (const float4*)(g_H3 + (size_t)r * 256);
    float4 v0 = row[lane * 2], v1 = row[lane * 2 + 1];
    float ss = v0.x * v0.x + v0.y * v0.y + v0.z * v0.z + v0.w * v0.w
             + v1.x * v1.x + v1.y * v1.y + v1.z * v1.z + v1.w * v1.w;
#pragma unroll
    for (int o = 16; o; o >>= 1) ss += __shfl_xor_sync(0xffffffffu, ss, o);
    float inv = 1.0f / fmaxf(sqrtf(ss), 1e-12f);
    v0.x *= inv; v0.y *= inv; v0.z *= inv; v0.w *= inv;
    v1.x *= inv; v1.y *= inv; v1.z *= inv; v1.w *= inv;
    float4* orow = (float4*)(out + (size_t)r * 256);
    orow[lane * 2]     = v0;
    orow[lane * 2 + 1] = v1;
    if (lane == 0 && out_size >= MTOT * ANCH_DIM + MTOT)
        out[MTOT * ANCH_DIM + r] = (float)g_ycls[r];
}

// ---------------------------------------------------------------------------
extern "C" void kernel_launch(void* const* d_in, const int* in_sizes, int n_in,
                              void* d_out, int out_size)
{
    const float* feats    = (const float*)d_in[0];
    const float* labels   = (const float*)d_in[1];
    const int*   predicts = (const int*)  d_in[2];
    const float* w1 = (const float*)d_in[3];
    const float* b1 = (const float*)d_in[4];
    const float* w2 = (const float*)d_in[5];
    const float* b2 = (const float*)d_in[6];
    const float* w3 = (const float*)d_in[7];
    const float* b3 = (const float*)d_in[8];
    float* out = (float*)d_out;

    cudaFuncSetAttribute(mma_gemm<1>, cudaFuncAttributeMaxDynamicSharedMemorySize, 2 * STAGE_B);
    cudaFuncSetAttribute(mma_gemm<0>, cudaFuncAttributeMaxDynamicSharedMemorySize, 2 * STAGE_B);

    __nv_bfloat16 *Xc, *H1c, *H2c, *W1c, *W2c, *W3c;
    cudaGetSymbolAddress((void**)&Xc,  g_Xc);
    cudaGetSymbolAddress((void**)&H1c, g_H1c);
    cudaGetSymbolAddress((void**)&H2c, g_H2c);
    cudaGetSymbolAddress((void**)&W1c, g_W1c);
    cudaGetSymbolAddress((void**)&W2c, g_W2c);
    cudaGetSymbolAddress((void**)&W3c, g_W3c);
    float* H3;
    cudaGetSymbolAddress((void**)&H3, g_H3);

    argmax_kernel<<<NPIX / 256, 256>>>(labels);
    select_kernel<<<NCLASS, 512>>>(predicts);
    gather_split_kernel<<<MTOT / 8, 256>>>(feats);
    wsplit_all<<<1792, 256>>>(w1, w2, w3);

    // layer 1: [12288,512] -> [12288,512], leaky, split store
    mma_gemm<1><<<dim3(8, 96), 256, 2 * STAGE_B>>>(Xc,  W1c, b1, 512, 16, H1c, nullptr);
    // layer 2: [12288,512] -> [12288,256], leaky, split store
    mma_gemm<1><<<dim3(4, 96), 256, 2 * STAGE_B>>>(H1c, W2c, b2, 512, 16, H2c, nullptr);
    // layer 3: [12288,256] -> [12288,256], linear, fp32 store
    mma_gemm<0><<<dim3(4, 96), 256, 2 * STAGE_B>>>(H2c, W3c, b3, 256, 8, nullptr, H3);

    norm_kernel<<<MTOT / 8, 256>>>(out, out_size);
}